// round 10
// baseline (speedup 1.0000x reference)
#include <cuda_runtime.h>
#include <cuda_bf16.h>
#include <cstdint>
#include <cstddef>

#define DINL __device__ __forceinline__

// ---------------------------------------------------------------------------
// HoMESecondLayer v10: ROWS=128 / 512 threads / 1 CTA per SM.
// bf16 mma.m16n8k16 + ldmatrix, full-K weight staging (2 syncs/GEMM),
// fused single-pass-z gating. All per-CTA fixed costs amortized over 2x rows.
// ---------------------------------------------------------------------------

constexpr int ROWS    = 128;
constexpr int THREADS = 512;
constexpr int META    = 128;
constexpr int GIN     = 256;

// bf16 weight images: W^T as [N][K], row-major K-contiguous.
constexpr int IW1 = 0;                    // 6 x [128][256]
constexpr int IW2 = IW1 + 6 * 128 * 256;  // 6 x [64][128]
constexpr int IW3 = IW2 + 6 * 64 * 128;   // 6 x [64][64]
constexpr int ITG = IW3 + 6 * 64 * 64;    // 4 x [64][256]
constexpr int IT1 = ITG + 4 * 64 * 256;   // 4 x [64][64]
constexpr int ITOT = IT1 + 4 * 64 * 64;
__device__ __align__(16) __nv_bfloat16 g_wimg[ITOT];

// smem layout (byte offsets)
constexpr int OFF_WST = 0;        // weight stage, max 128 x 17 uint4 = 34816
constexpr int OFF_A   = 34816;    // bf16 words 128*68 = 34816 (gating: slab x2)
constexpr int OFF_B   = 69632;    // bf16 words 128*36 = 18432
constexpr int OFF_CFP = 88064;    // float 128*66 = 33792
constexpr int OFF_CMB = 121856;   // bf16 words 128*132 = 67584 (end 189440)
constexpr int OFF_GW  = 189440;   // float 128*4 = 2048
constexpr int SMEM_TOTAL = 191488;
// overlays (temporally disjoint)
constexpr int OFF_R   = OFF_CFP;  // rank-8 r, gating phase only
constexpr int OFF_LG  = OFF_B;    // task-gate logits, pre-expert only
constexpr int SLAB_BYTES = 18432; // slab buffer (128 x 36 floats)

// pitches
constexpr int P_CM = 132;  // words; 33*16B, 33%8=1 -> LDSM conflict-free
constexpr int P_A  = 68;   // 17*16B
constexpr int P_B  = 36;   // 9*16B
constexpr int P_CF = 66;   // floats
constexpr int P_SL = 36;   // slab pitch (floats)

DINL float sigm(float x)   { return 1.0f / (1.0f + __expf(-x)); }
DINL float swishf(float x) { return x   / (1.0f + __expf(-x)); }
DINL uint32_t sm_addr(const void* p) {
    return (uint32_t)__cvta_generic_to_shared(p);
}
DINL void mma16(float* d, const uint32_t* a, uint32_t b0, uint32_t b1) {
    asm volatile(
        "mma.sync.aligned.m16n8k16.row.col.f32.bf16.bf16.f32 "
        "{%0,%1,%2,%3},{%4,%5,%6,%7},{%8,%9},{%0,%1,%2,%3};"
        : "+f"(d[0]), "+f"(d[1]), "+f"(d[2]), "+f"(d[3])
        : "r"(a[0]), "r"(a[1]), "r"(a[2]), "r"(a[3]), "r"(b0), "r"(b1));
}
DINL void ldsm4(uint32_t& r0, uint32_t& r1, uint32_t& r2, uint32_t& r3,
                uint32_t addr) {
    asm volatile(
        "ldmatrix.sync.aligned.m8n8.x4.shared.b16 {%0,%1,%2,%3}, [%4];"
        : "=r"(r0), "=r"(r1), "=r"(r2), "=r"(r3) : "r"(addr));
}
DINL uint32_t packbf(float lo, float hi) {
    __nv_bfloat162 p = __floats2bfloat162_rn(lo, hi);
    return *reinterpret_cast<uint32_t*>(&p);
}

// ---- single merged prep: all W[K][N] fp32 -> bf16 W^T [N][K] images -------
__global__ void prep_all(const float* __restrict__ eW1,
                         const float* __restrict__ eW2,
                         const float* __restrict__ eW3,
                         const float* __restrict__ tgW1,
                         const float* __restrict__ twW1)
{
    // segment table: {imgOff, srcPtr-id, K, N, count}
    const int SZ1 = 6 * 128 * 256, SZ2 = 6 * 64 * 128, SZ3 = 6 * 64 * 64;
    const int SZ4 = 4 * 64 * 256,  SZ5 = 4 * 64 * 64;
    const int total = SZ1 + SZ2 + SZ3 + SZ4 + SZ5;
    for (int gi = blockIdx.x * blockDim.x + threadIdx.x; gi < total;
         gi += gridDim.x * blockDim.x) {
        int idx = gi, dstOff, K, N;
        const float* src;
        if (idx < SZ1)                 { dstOff = IW1; src = eW1;  K = 256; N = 128; }
        else if ((idx -= SZ1) < SZ2)   { dstOff = IW2; src = eW2;  K = 128; N = 64; }
        else if ((idx -= SZ2) < SZ3)   { dstOff = IW3; src = eW3;  K = 64;  N = 64; }
        else if ((idx -= SZ3) < SZ4)   { dstOff = ITG; src = tgW1; K = 256; N = 64; }
        else         { idx -= SZ4;       dstOff = IT1; src = twW1; K = 64;  N = 64; }
        const int m   = idx / (K * N);
        const int rem = idx - m * (K * N);
        const int n   = rem / K;
        const int k   = rem - n * K;
        g_wimg[dstOff + idx] = __float2bfloat16(src[(size_t)m * K * N + k * N + n]);
    }
}

// ---------------------------------------------------------------------------
// C[128][N] = act(A[128][K] @ W[K][N] + bias).
// Full-K (or 128-K-chunked) weight staging; entry sync doubles as the
// dependency sync with the previous GEMM/epilogue; NO trailing sync.
// 16 warps: (N>=128) 4 colx4 Mgroups(32r, MT=2); else 2 colx8 Mgroups(16r).
// ---------------------------------------------------------------------------
template<int N, int K, int CHK, int AP2, bool SW, bool OUTBF, int CP>
DINL void gemm_mma(const uint32_t* As, const __nv_bfloat16* Wimg,
                   const float* __restrict__ bias, void* Cs,
                   char* smbase, int tid)
{
    constexpr int NCH   = K / CHK;
    constexpr int UPR   = CHK / 8;          // uint4 per staged row
    constexpr int P16   = UPR + 1;          // padded pitch in uint4
    constexpr int UNITS = N * UPR / THREADS;
    constexpr int WN    = (N >= 128) ? 4 : 2;
    constexpr int MT    = (N >= 128) ? 2 : 1;
    const int w = tid >> 5, lane = tid & 31;
    const int col0  = (w % WN) * 32;
    const int mrow0 = (w / WN) * (MT * 16);
    const int lrow = lane & 7, lg8 = (lane >> 3) & 1, lg16 = lane >> 4;
    const int r = lane >> 2, c = lane & 3;

    const uint32_t abase = sm_addr(As);
    uint32_t a_addr[MT];
#pragma unroll
    for (int mt = 0; mt < MT; mt++)
        a_addr[mt] = abase +
            ((mrow0 + mt * 16 + lg8 * 8 + lrow) * AP2 + lg16 * 4) * 4;
    const uint32_t wbase = sm_addr(smbase + OFF_WST);
    uint32_t b_addr[2];
#pragma unroll
    for (int p = 0; p < 2; p++)
        b_addr[p] = wbase +
            (uint32_t)(col0 + p * 16 + lg16 * 8 + lrow) * (P16 * 16) + lg8 * 16;

    float acc[MT][4][4];
#pragma unroll
    for (int mt = 0; mt < MT; mt++)
#pragma unroll
        for (int nt = 0; nt < 4; nt++)
#pragma unroll
            for (int i = 0; i < 4; i++) acc[mt][nt][i] = 0.f;

    const uint4* gsrc = reinterpret_cast<const uint4*>(Wimg);
    uint4* wst4 = reinterpret_cast<uint4*>(smbase + OFF_WST);
    uint4 pre[UNITS];
#pragma unroll
    for (int j = 0; j < UNITS; j++) {
        const int i = tid + j * THREADS;
        pre[j] = __ldg(&gsrc[(i / UPR) * (K / 8) + (i % UPR)]);
    }

#pragma unroll
    for (int kc = 0; kc < NCH; kc++) {
        __syncthreads();   // wst free + (kc==0) A ready from prior phase
#pragma unroll
        for (int j = 0; j < UNITS; j++) {
            const int i = tid + j * THREADS;
            wst4[(i / UPR) * P16 + (i % UPR)] = pre[j];
        }
        __syncthreads();
        if (kc + 1 < NCH) {
#pragma unroll
            for (int j = 0; j < UNITS; j++) {
                const int i = tid + j * THREADS;
                pre[j] = __ldg(&gsrc[(i / UPR) * (K / 8) + (kc + 1) * UPR + (i % UPR)]);
            }
        }
#pragma unroll
        for (int ks2 = 0; ks2 < CHK / 16; ks2++) {
            const int ksg = kc * (CHK / 16) + ks2;
            uint32_t af[MT][4];
#pragma unroll
            for (int mt = 0; mt < MT; mt++)
                ldsm4(af[mt][0], af[mt][1], af[mt][2], af[mt][3],
                      a_addr[mt] + ksg * 32);
            uint32_t bf[4][2];
#pragma unroll
            for (int p = 0; p < 2; p++)
                ldsm4(bf[2 * p][0], bf[2 * p][1], bf[2 * p + 1][0], bf[2 * p + 1][1],
                      b_addr[p] + ks2 * 32);
#pragma unroll
            for (int nt = 0; nt < 4; nt++)
#pragma unroll
                for (int mt = 0; mt < MT; mt++)
                    mma16(acc[mt][nt], af[mt], bf[nt][0], bf[nt][1]);
        }
    }

#pragma unroll
    for (int mt = 0; mt < MT; mt++) {
        const int row = mrow0 + mt * 16 + r;
#pragma unroll
        for (int nt = 0; nt < 4; nt++) {
            const int cn = col0 + nt * 8 + 2 * c;
            const float bb0 = __ldg(&bias[cn]), bb1 = __ldg(&bias[cn + 1]);
            float v0 = acc[mt][nt][0] + bb0, v1 = acc[mt][nt][1] + bb1;
            float v2 = acc[mt][nt][2] + bb0, v3 = acc[mt][nt][3] + bb1;
            if (SW) { v0 = swishf(v0); v1 = swishf(v1); v2 = swishf(v2); v3 = swishf(v3); }
            if (OUTBF) {
                uint32_t* C = reinterpret_cast<uint32_t*>(Cs);
                C[row * CP + (cn >> 1)]       = packbf(v0, v1);
                C[(row + 8) * CP + (cn >> 1)] = packbf(v2, v3);
            } else {
                float* C = reinterpret_cast<float*>(Cs);
                C[row * CP + cn] = v0; C[row * CP + cn + 1] = v1;
                C[(row + 8) * CP + cn] = v2; C[(row + 8) * CP + cn + 1] = v3;
            }
        }
    }
}

// small SIMT gemm for tower layer 2 (N=32)
DINL void gemm_t2(const float* As, const float* __restrict__ Wg,
                  const float* __restrict__ bg, float* Cs, int tid)
{
    constexpr int CT = 8, TM = 2;   // 64 row-threads x 2 rows = 128 rows
    const int tc = tid % CT, tr = tid / CT;
    const int col = tc * 4;
    float acc[TM][4];
#pragma unroll
    for (int m = 0; m < TM; m++) {
        acc[m][0] = 0.f; acc[m][1] = 0.f; acc[m][2] = 0.f; acc[m][3] = 0.f;
    }
    for (int k = 0; k < 64; k++) {
        const float4 wv = __ldg(reinterpret_cast<const float4*>(Wg + (size_t)k * 32 + col));
#pragma unroll
        for (int m = 0; m < TM; m++) {
            const float a = As[(tr * TM + m) * P_CF + k];
            acc[m][0] = fmaf(a, wv.x, acc[m][0]);
            acc[m][1] = fmaf(a, wv.y, acc[m][1]);
            acc[m][2] = fmaf(a, wv.z, acc[m][2]);
            acc[m][3] = fmaf(a, wv.w, acc[m][3]);
        }
    }
    const float4 bv = __ldg(reinterpret_cast<const float4*>(bg + col));
#pragma unroll
    for (int m = 0; m < TM; m++) {
        float* cp = Cs + (tr * TM + m) * P_B + col;
        cp[0] = swishf(acc[m][0] + bv.x);
        cp[1] = swishf(acc[m][1] + bv.y);
        cp[2] = swishf(acc[m][2] + bv.z);
        cp[3] = swishf(acc[m][3] + bv.w);
    }
}

__global__ __launch_bounds__(THREADS, 1)
void home_kernel(
    const float* __restrict__ z_shared, const float* __restrict__ z_g0,
    const float* __restrict__ z_g1,
    const float* __restrict__ exp_b1, const float* __restrict__ exp_b2,
    const float* __restrict__ exp_b3,
    const float* __restrict__ ln_s,   const float* __restrict__ ln_b,
    const float* __restrict__ fg_A,   const float* __restrict__ fg_B,
    const float* __restrict__ tg_b1,
    const float* __restrict__ tg_W2,  const float* __restrict__ tg_b2,
    const float* __restrict__ sg_W,   const float* __restrict__ sg_b,
    const float* __restrict__ tw_b1,
    const float* __restrict__ tw_W2,  const float* __restrict__ tw_b2,
    const float* __restrict__ tw_W3,  const float* __restrict__ tw_b3,
    float* __restrict__ out)
{
    extern __shared__ char sm[];
    float*    fga  = reinterpret_cast<float*>(sm + OFF_WST);          // [256][8]
    float*    fgb  = reinterpret_cast<float*>(sm + OFF_WST + 8192);   // [8][256]
    float*    slab0 = reinterpret_cast<float*>(sm + OFF_A);
    float*    slab1 = reinterpret_cast<float*>(sm + OFF_A + SLAB_BYTES);
    uint32_t* cmw  = reinterpret_cast<uint32_t*>(sm + OFF_CMB);
    uint32_t* aw   = reinterpret_cast<uint32_t*>(sm + OFF_A);
    uint32_t* bw   = reinterpret_cast<uint32_t*>(sm + OFF_B);
    float*    cfp  = reinterpret_cast<float*>(sm + OFF_CFP);
    float*    rb   = reinterpret_cast<float*>(sm + OFF_R);
    float*    gwb  = reinterpret_cast<float*>(sm + OFF_GW);
    float*    lgb  = reinterpret_cast<float*>(sm + OFF_LG);
    float*    twh2 = reinterpret_cast<float*>(sm + OFF_B);

    const int tid  = threadIdx.x;
    const int wid  = tid >> 5, lane = tid & 31;
    const int t    = blockIdx.y;
    const int g    = t >> 1;                    // TASK_TO_GROUP = {0,0,1,1}
    const int row0 = blockIdx.x * ROWS;
    const float* zg = g ? z_g1 : z_g0;

    // ---- stage fgA [256][8], fgB [8][256] into smem ----------------------
    {
        const float4* A4 = reinterpret_cast<const float4*>(fg_A + (size_t)t * 2048);
        const float4* B4 = reinterpret_cast<const float4*>(fg_B + (size_t)t * 2048);
        float4* fa4 = reinterpret_cast<float4*>(fga);
        float4* fb4 = reinterpret_cast<float4*>(fgb);
        if (tid < 512) {
            fa4[tid] = __ldg(&A4[tid]);
            fb4[tid] = __ldg(&B4[tid]);
        }
    }

    // ---- pass 1: double-buffered slab; racc = cm @ fgA; pack UNGATED cm --
    const int grow = tid >> 2;            // 0..127
    const int jp   = (tid & 3) * 2;       // 0,2,4,6
    float r0 = 0.f, r1 = 0.f;
    {   // stage chunk 0 -> slab0 (128 rows x 32 cols = 1024 float4)
#pragma unroll
        for (int j = 0; j < 2; j++) {
            const int i = tid + j * THREADS;
            *reinterpret_cast<float4*>(&slab0[(i >> 3) * P_SL + (i & 7) * 4]) =
                *reinterpret_cast<const float4*>(
                    z_shared + (size_t)(row0 + (i >> 3)) * META + (i & 7) * 4);
        }
    }
#pragma unroll 1
    for (int ch = 0; ch < 8; ch++) {
        __syncthreads();
        const float* cur = (ch & 1) ? slab1 : slab0;
        float4 zr[2];
        const bool more = (ch < 7);
        if (more) {
            const float* zsrc = (ch + 1 < 4) ? z_shared : zg;
            const int cb = ((ch + 1) & 3) * 32;
#pragma unroll
            for (int j = 0; j < 2; j++) {
                const int i = tid + j * THREADS;
                zr[j] = *reinterpret_cast<const float4*>(
                    zsrc + (size_t)(row0 + (i >> 3)) * META + cb + (i & 7) * 4);
            }
        }
#pragma unroll 8
        for (int k = 0; k < 32; k++) {
            const float a = cur[grow * P_SL + k];
            const float2 f = *reinterpret_cast<const float2*>(
                &fga[(ch * 32 + k) * 8 + jp]);
            r0 = fmaf(a, f.x, r0);
            r1 = fmaf(a, f.y, r1);
        }
#pragma unroll
        for (int i2 = 0; i2 < 4; i2++) {
            const int p = tid + i2 * THREADS;
            const int row = p >> 4, pp = p & 15;
            const float2 v = *reinterpret_cast<const float2*>(
                &cur[row * P_SL + 2 * pp]);
            cmw[row * P_CM + ch * 16 + pp] = packbf(v.x, v.y);
        }
        if (more) {
            float* nxt = (ch & 1) ? slab0 : slab1;
#pragma unroll
            for (int j = 0; j < 2; j++) {
                const int i = tid + j * THREADS;
                *reinterpret_cast<float4*>(&nxt[(i >> 3) * P_SL + (i & 7) * 4]) = zr[j];
            }
        }
    }
    rb[grow * 8 + jp]     = r0;
    rb[grow * 8 + jp + 1] = r1;
    __syncthreads();

    // ---- pass 2: gate cmw in place (no global reads) ----------------------
#pragma unroll 4
    for (int i = 0; i < 32; i++) {
        const int p = tid + i * THREADS;
        const int row = p >> 7, pp = p & 127;
        const uint32_t word = cmw[row * P_CM + pp];
        __nv_bfloat162 bv = *reinterpret_cast<const __nv_bfloat162*>(&word);
        const float2 f = __bfloat1622float2(bv);
        const float* rr = &rb[row * 8];
        float d0 = 0.f, d1 = 0.f;
#pragma unroll
        for (int j = 0; j < 8; j++) {
            const float2 b = *reinterpret_cast<const float2*>(
                &fgb[j * 256 + 2 * pp]);
            d0 = fmaf(rr[j], b.x, d0);
            d1 = fmaf(rr[j], b.y, d1);
        }
        cmw[row * P_CM + pp] =
            packbf(f.x * 2.0f * sigm(d0), f.y * 2.0f * sigm(d1));
    }
    // no sync: tg gemm entry sync orders cmw writes before ldsm reads

    // ---- 3. task gate (full-K staged) -------------------------------------
    gemm_mma<64, 256, 256, P_CM, true, false, P_CF>(
        cmw, g_wimg + ITG + t * 16384, tg_b1 + t * 64, cfp, sm, tid);
    __syncthreads();
    {
        const int row = tid >> 2, j = tid & 3;
        const float* W = tg_W2 + (size_t)t * 64 * 4;
        float acc = __ldg(&tg_b2[t * 4 + j]);
#pragma unroll 4
        for (int c2 = 0; c2 < 64; c2++)
            acc = fmaf(cfp[row * P_CF + c2], __ldg(&W[c2 * 4 + j]), acc);
        lgb[row * 4 + j] = acc;
    }
    __syncthreads();
    if (tid < ROWS) {
        const float l0 = lgb[tid * 4 + 0], l1 = lgb[tid * 4 + 1];
        const float l2 = lgb[tid * 4 + 2], l3 = lgb[tid * 4 + 3];
        const float m  = fmaxf(fmaxf(l0, l1), fmaxf(l2, l3));
        const float e0 = __expf(l0 - m), e1 = __expf(l1 - m);
        const float e2 = __expf(l2 - m), e3 = __expf(l3 - m);
        const float inv = 1.0f / (e0 + e1 + e2 + e3);
        gwb[tid * 4 + 0] = e0 * inv; gwb[tid * 4 + 1] = e1 * inv;
        gwb[tid * 4 + 2] = e2 * inv; gwb[tid * 4 + 3] = e3 * inv;
    }
    // no sync: W1 entry sync orders gwb (read in epilogue after W3)

    // ---- 4. experts --------------------------------------------------------
    float ag0[8], ag1[8];
#pragma unroll 1
    for (int ep = 0; ep < 4; ep++) {
        const int e = (ep < 2) ? ep : (ep + 2 * g);

        gemm_mma<128, 256, 128, P_CM, true, true, P_A>(
            cmw, g_wimg + IW1 + e * 32768, exp_b1 + e * 128, aw, sm, tid);
        gemm_mma<64, 128, 128, P_A, true, true, P_B>(
            aw, g_wimg + IW2 + e * 8192, exp_b2 + e * 64, bw, sm, tid);
        gemm_mma<64, 64, 64, P_B, false, false, P_CF>(
            bw, g_wimg + IW3 + e * 4096, exp_b3 + e * 64, cfp, sm, tid);
        __syncthreads();

        {
            const float* lS  = ln_s + e * 64;
            const float* lB  = ln_b + e * 64;
            const float* sgw = sg_W + (size_t)t * 256;
            const float  sgb = __ldg(&sg_b[t * 4 + ep]);
            const int c0 = 2 * lane, c1 = 2 * lane + 1;
#pragma unroll
            for (int rr = 0; rr < 8; rr++) {
                const int row = wid * 8 + rr;
                const float2 v = *reinterpret_cast<const float2*>(&cfp[row * P_CF + c0]);
                float sum = v.x + v.y;
                float sq  = fmaf(v.x, v.x, v.y * v.y);
#pragma unroll
                for (int o = 16; o; o >>= 1) {
                    sum += __shfl_xor_sync(0xffffffffu, sum, o);
                    sq  += __shfl_xor_sync(0xffffffffu, sq,  o);
                }
                const float mu  = sum * (1.0f / 64.0f);
                const float var = sq * (1.0f / 64.0f) - mu * mu;
                const float inv = rsqrtf(var + 1e-5f);
                const float n0  = fmaf((v.x - mu) * inv, __ldg(&lS[c0]), __ldg(&lB[c0]));
                const float n1  = fmaf((v.y - mu) * inv, __ldg(&lS[c1]), __ldg(&lB[c1]));
                float swp = fmaf(n0, __ldg(&sgw[c0 * 4 + ep]),
                                 n1 * __ldg(&sgw[c1 * 4 + ep]));
#pragma unroll
                for (int o = 16; o; o >>= 1)
                    swp += __shfl_xor_sync(0xffffffffu, swp, o);
                const float scale = (swp + sgb) * gwb[row * 4 + ep];
                if (ep == 0) { ag0[rr] = n0 * scale;               ag1[rr] = n1 * scale; }
                else         { ag0[rr] = fmaf(n0, scale, ag0[rr]); ag1[rr] = fmaf(n1, scale, ag1[rr]); }
            }
        }
        // no sync: next gemm's entry sync covers the dependency
    }

    // ---- agg -> bf16 bw (tower entry sync orders) -------------------------
#pragma unroll
    for (int rr = 0; rr < 8; rr++) {
        const int row = wid * 8 + rr;
        bw[row * P_B + lane] = packbf(ag0[rr], ag1[rr]);
    }

    // ---- 5. tower ----------------------------------------------------------
    gemm_mma<64, 64, 64, P_B, true, false, P_CF>(
        bw, g_wimg + IT1 + t * 4096, tw_b1 + t * 64, cfp, sm, tid);
    __syncthreads();
    gemm_t2(cfp, tw_W2 + (size_t)t * 64 * 32, tw_b2 + t * 32, twh2, tid);
    __syncthreads();
    if (tid < ROWS) {
        const float* th = &twh2[tid * P_B];
        const float* W  = tw_W3 + t * 32;
        float acc = __ldg(&tw_b3[t]);
#pragma unroll 4
        for (int c2 = 0; c2 < 32; c2++)
            acc = fmaf(th[c2], __ldg(&W[c2]), acc);
        out[(size_t)(row0 + tid) * 4 + t] = sigm(acc);
    }
}

extern "C" void kernel_launch(void* const* d_in, const int* in_sizes, int n_in,
                              void* d_out, int out_size)
{
    (void)n_in; (void)out_size;
    const float* zs   = (const float*)d_in[0];
    const float* z0   = (const float*)d_in[1];
    const float* z1   = (const float*)d_in[2];
    const float* eW1  = (const float*)d_in[4];
    const float* eb1  = (const float*)d_in[5];
    const float* eW2  = (const float*)d_in[6];
    const float* eb2  = (const float*)d_in[7];
    const float* eW3  = (const float*)d_in[8];
    const float* eb3  = (const float*)d_in[9];
    const float* lns  = (const float*)d_in[10];
    const float* lnb  = (const float*)d_in[11];
    const float* fgA  = (const float*)d_in[12];
    const float* fgB  = (const float*)d_in[13];
    const float* tgW1 = (const float*)d_in[14];
    const float* tgb1 = (const float*)d_in[15];
    const float* tgW2 = (const float*)d_in[16];
    const float* tgb2 = (const float*)d_in[17];
    const float* sgW  = (const float*)d_in[18];
    const float* sgb  = (const float*)d_in[19];
    const float* twW1 = (const float*)d_in[20];
    const float* twb1 = (const float*)d_in[21];
    const float* twW2 = (const float*)d_in[22];
    const float* twb2 = (const float*)d_in[23];
    const float* twW3 = (const float*)d_in[24];
    const float* twb3 = (const float*)d_in[25];

    const int Bn = in_sizes[0] / META;

    prep_all<<<296, 256>>>(eW1, eW2, eW3, tgW1, twW1);

    cudaFuncSetAttribute(home_kernel, cudaFuncAttributeMaxDynamicSharedMemorySize,
                         SMEM_TOTAL);
    dim3 grid(Bn / ROWS, 4);
    home_kernel<<<grid, THREADS, SMEM_TOTAL>>>(
        zs, z0, z1, eb1, eb2, eb3, lns, lnb, fgA, fgB,
        tgb1, tgW2, tgb2, sgW, sgb, twb1, twW2, twb2, twW3, twb3,
        (float*)d_out);
}

// round 11
// speedup vs baseline: 1.0470x; 1.0470x over previous
#include <cuda_runtime.h>
#include <cuda_bf16.h>
#include <cstdint>
#include <cstddef>

#define DINL __device__ __forceinline__

// ---------------------------------------------------------------------------
// HoMESecondLayer v11: ROWS=128 / 512 threads / 1 CTA per SM.
// bf16 mma.m16n8k16 + ldmatrix; cp.async double-buffered weight pipeline
// (fetch overlaps MMA); tanh-based activations (1 MUFU); vectorized gating.
// ---------------------------------------------------------------------------

constexpr int ROWS    = 128;
constexpr int THREADS = 512;
constexpr int META    = 128;
constexpr int GIN     = 256;

// bf16 weight images: W^T as [N][K], row-major K-contiguous.
constexpr int IW1 = 0;                    // 6 x [128][256]
constexpr int IW2 = IW1 + 6 * 128 * 256;  // 6 x [64][128]
constexpr int IW3 = IW2 + 6 * 64 * 128;   // 6 x [64][64]
constexpr int ITG = IW3 + 6 * 64 * 64;    // 4 x [64][256]
constexpr int IT1 = ITG + 4 * 64 * 256;   // 4 x [64][64]
constexpr int ITOT = IT1 + 4 * 64 * 64;
__device__ __align__(16) __nv_bfloat16 g_wimg[ITOT];

// smem layout (byte offsets)
constexpr int OFF_WST0 = 0;        // weight ring buf 0 (34816)
constexpr int OFF_WST1 = 34816;    // weight ring buf 1 (34816)
constexpr int OFF_A    = 69632;    // bf16 words 128*68 = 34816 (gating: slabs)
constexpr int OFF_B    = 104448;   // bf16 words 128*36 = 18432
constexpr int OFF_CFP  = 122880;   // float 128*66 = 33792 (gating: fga/fgb)
constexpr int OFF_CMB  = 156672;   // bf16 words 128*132 = 67584
constexpr int OFF_GW   = 224256;   // float 128*4 = 2048
constexpr int SMEM_TOTAL = 226304;
constexpr int SLAB_BYTES = 18432;

// pitches
constexpr int P_CM = 132;  // words; 33*16B, 33%8=1 -> LDSM conflict-free
constexpr int P_A  = 68;   // 17*16B
constexpr int P_B  = 36;   // 9*16B
constexpr int P_CF = 66;   // floats
constexpr int P_SL = 36;   // slab pitch (floats)

DINL float tanh_ap(float x) {
    float y; asm("tanh.approx.f32 %0, %1;" : "=f"(y) : "f"(x)); return y;
}
DINL float sigm(float x)   { return fmaf(tanh_ap(0.5f * x), 0.5f, 0.5f); }
DINL float swishf(float x) { return x * sigm(x); }
DINL uint32_t sm_addr(const void* p) {
    return (uint32_t)__cvta_generic_to_shared(p);
}
DINL void mma16(float* d, const uint32_t* a, uint32_t b0, uint32_t b1) {
    asm volatile(
        "mma.sync.aligned.m16n8k16.row.col.f32.bf16.bf16.f32 "
        "{%0,%1,%2,%3},{%4,%5,%6,%7},{%8,%9},{%0,%1,%2,%3};"
        : "+f"(d[0]), "+f"(d[1]), "+f"(d[2]), "+f"(d[3])
        : "r"(a[0]), "r"(a[1]), "r"(a[2]), "r"(a[3]), "r"(b0), "r"(b1));
}
DINL void ldsm4(uint32_t& r0, uint32_t& r1, uint32_t& r2, uint32_t& r3,
                uint32_t addr) {
    asm volatile(
        "ldmatrix.sync.aligned.m8n8.x4.shared.b16 {%0,%1,%2,%3}, [%4];"
        : "=r"(r0), "=r"(r1), "=r"(r2), "=r"(r3) : "r"(addr));
}
DINL uint32_t packbf(float lo, float hi) {
    __nv_bfloat162 p = __floats2bfloat162_rn(lo, hi);
    return *reinterpret_cast<uint32_t*>(&p);
}
DINL float2 unpkbf(uint32_t w) {
    __nv_bfloat162 b = *reinterpret_cast<__nv_bfloat162*>(&w);
    return __bfloat1622float2(b);
}
DINL void cp16(uint32_t dst, const void* src) {
    asm volatile("cp.async.cg.shared.global [%0], [%1], 16;"
                 :: "r"(dst), "l"(src));
}
DINL void cp_commit() { asm volatile("cp.async.commit_group;" ::: "memory"); }
DINL void cp_wait0()  { asm volatile("cp.async.wait_group 0;" ::: "memory"); }

// ---- single merged prep: all W[K][N] fp32 -> bf16 W^T [N][K] images -------
__global__ void prep_all(const float* __restrict__ eW1,
                         const float* __restrict__ eW2,
                         const float* __restrict__ eW3,
                         const float* __restrict__ tgW1,
                         const float* __restrict__ twW1)
{
    const int SZ1 = 6 * 128 * 256, SZ2 = 6 * 64 * 128, SZ3 = 6 * 64 * 64;
    const int SZ4 = 4 * 64 * 256,  SZ5 = 4 * 64 * 64;
    const int total = SZ1 + SZ2 + SZ3 + SZ4 + SZ5;
    for (int gi = blockIdx.x * blockDim.x + threadIdx.x; gi < total;
         gi += gridDim.x * blockDim.x) {
        int idx = gi, dstOff, K, N;
        const float* src;
        if (idx < SZ1)                 { dstOff = IW1; src = eW1;  K = 256; N = 128; }
        else if ((idx -= SZ1) < SZ2)   { dstOff = IW2; src = eW2;  K = 128; N = 64; }
        else if ((idx -= SZ2) < SZ3)   { dstOff = IW3; src = eW3;  K = 64;  N = 64; }
        else if ((idx -= SZ3) < SZ4)   { dstOff = ITG; src = tgW1; K = 256; N = 64; }
        else         { idx -= SZ4;       dstOff = IT1; src = twW1; K = 64;  N = 64; }
        const int m   = idx / (K * N);
        const int rem = idx - m * (K * N);
        const int n   = rem / K;
        const int k   = rem - n * K;
        g_wimg[dstOff + idx] = __float2bfloat16(src[(size_t)m * K * N + k * N + n]);
    }
}

// ---- cp.async stage of one weight chunk into a ring buffer ----------------
// NR rows, UPR uint4 per row in this chunk, KU = K/8 (uint4 per image row).
template<int NR, int UPR, int KU>
DINL void stage_chunk(uint32_t dst, const __nv_bfloat16* Wimg, int kc, int tid)
{
    constexpr int P16   = UPR + 1;
    constexpr int UNITS = NR * UPR / THREADS;
    const uint4* gsrc = reinterpret_cast<const uint4*>(Wimg);
#pragma unroll
    for (int j = 0; j < UNITS; j++) {
        const int i = tid + j * THREADS;
        cp16(dst + (uint32_t)((i / UPR) * P16 + (i % UPR)) * 16,
             gsrc + (i / UPR) * KU + kc * UPR + (i % UPR));
    }
    cp_commit();
}

// ---- MMA over one staged chunk (CHK K-cols) -------------------------------
template<int N, int CHK, int AP2>
DINL void mma_chunk(float acc[][4][4], const uint32_t* As, uint32_t buf,
                    int kc, int tid)
{
    constexpr int WN  = (N >= 128) ? 4 : 2;
    constexpr int MT  = (N >= 128) ? 2 : 1;
    constexpr int P16 = CHK / 8 + 1;
    const int w = tid >> 5, lane = tid & 31;
    const int col0  = (w % WN) * 32;
    const int mrow0 = (w / WN) * (MT * 16);
    const int lrow = lane & 7, lg8 = (lane >> 3) & 1, lg16 = lane >> 4;

    const uint32_t abase = sm_addr(As);
    uint32_t a_addr[MT];
#pragma unroll
    for (int mt = 0; mt < MT; mt++)
        a_addr[mt] = abase +
            ((mrow0 + mt * 16 + lg8 * 8 + lrow) * AP2 + lg16 * 4) * 4;
    uint32_t b_addr[2];
#pragma unroll
    for (int p = 0; p < 2; p++)
        b_addr[p] = buf +
            (uint32_t)(col0 + p * 16 + lg16 * 8 + lrow) * (P16 * 16) + lg8 * 16;

#pragma unroll
    for (int ks2 = 0; ks2 < CHK / 16; ks2++) {
        const int ksg = kc * (CHK / 16) + ks2;
        uint32_t af[MT][4];
#pragma unroll
        for (int mt = 0; mt < MT; mt++)
            ldsm4(af[mt][0], af[mt][1], af[mt][2], af[mt][3],
                  a_addr[mt] + ksg * 32);
        uint32_t bf[4][2];
#pragma unroll
        for (int p = 0; p < 2; p++)
            ldsm4(bf[2 * p][0], bf[2 * p][1], bf[2 * p + 1][0], bf[2 * p + 1][1],
                  b_addr[p] + ks2 * 32);
#pragma unroll
        for (int nt = 0; nt < 4; nt++)
#pragma unroll
            for (int mt = 0; mt < MT; mt++)
                mma16(acc[mt][nt], af[mt], bf[nt][0], bf[nt][1]);
    }
}

// ---- epilogue: bias (+swish), store fp32 or packed bf16 -------------------
template<int N, bool SW, bool OUTBF, int CP>
DINL void epilogue(float acc[][4][4], const float* __restrict__ bias,
                   void* Cs, int tid)
{
    constexpr int WN = (N >= 128) ? 4 : 2;
    constexpr int MT = (N >= 128) ? 2 : 1;
    const int w = tid >> 5, lane = tid & 31;
    const int col0  = (w % WN) * 32;
    const int mrow0 = (w / WN) * (MT * 16);
    const int r = lane >> 2, c = lane & 3;
#pragma unroll
    for (int mt = 0; mt < MT; mt++) {
        const int row = mrow0 + mt * 16 + r;
#pragma unroll
        for (int nt = 0; nt < 4; nt++) {
            const int cn = col0 + nt * 8 + 2 * c;
            const float bb0 = __ldg(&bias[cn]), bb1 = __ldg(&bias[cn + 1]);
            float v0 = acc[mt][nt][0] + bb0, v1 = acc[mt][nt][1] + bb1;
            float v2 = acc[mt][nt][2] + bb0, v3 = acc[mt][nt][3] + bb1;
            if (SW) { v0 = swishf(v0); v1 = swishf(v1); v2 = swishf(v2); v3 = swishf(v3); }
            if (OUTBF) {
                uint32_t* C = reinterpret_cast<uint32_t*>(Cs);
                C[row * CP + (cn >> 1)]       = packbf(v0, v1);
                C[(row + 8) * CP + (cn >> 1)] = packbf(v2, v3);
            } else {
                float* C = reinterpret_cast<float*>(Cs);
                C[row * CP + cn] = v0; C[row * CP + cn + 1] = v1;
                C[(row + 8) * CP + cn] = v2; C[(row + 8) * CP + cn + 1] = v3;
            }
        }
    }
}

// small SIMT gemm for tower layer 2 (N=32)
DINL void gemm_t2(const float* As, const float* __restrict__ Wg,
                  const float* __restrict__ bg, float* Cs, int tid)
{
    constexpr int CT = 8, TM = 2;
    const int tc = tid % CT, tr = tid / CT;
    const int col = tc * 4;
    float acc[TM][4];
#pragma unroll
    for (int m = 0; m < TM; m++) {
        acc[m][0] = 0.f; acc[m][1] = 0.f; acc[m][2] = 0.f; acc[m][3] = 0.f;
    }
    for (int k = 0; k < 64; k++) {
        const float4 wv = __ldg(reinterpret_cast<const float4*>(Wg + (size_t)k * 32 + col));
#pragma unroll
        for (int m = 0; m < TM; m++) {
            const float a = As[(tr * TM + m) * P_CF + k];
            acc[m][0] = fmaf(a, wv.x, acc[m][0]);
            acc[m][1] = fmaf(a, wv.y, acc[m][1]);
            acc[m][2] = fmaf(a, wv.z, acc[m][2]);
            acc[m][3] = fmaf(a, wv.w, acc[m][3]);
        }
    }
    const float4 bv = __ldg(reinterpret_cast<const float4*>(bg + col));
#pragma unroll
    for (int m = 0; m < TM; m++) {
        float* cp = Cs + (tr * TM + m) * P_B + col;
        cp[0] = swishf(acc[m][0] + bv.x);
        cp[1] = swishf(acc[m][1] + bv.y);
        cp[2] = swishf(acc[m][2] + bv.z);
        cp[3] = swishf(acc[m][3] + bv.w);
    }
}

__global__ __launch_bounds__(THREADS, 1)
void home_kernel(
    const float* __restrict__ z_shared, const float* __restrict__ z_g0,
    const float* __restrict__ z_g1,
    const float* __restrict__ exp_b1, const float* __restrict__ exp_b2,
    const float* __restrict__ exp_b3,
    const float* __restrict__ ln_s,   const float* __restrict__ ln_b,
    const float* __restrict__ fg_A,   const float* __restrict__ fg_B,
    const float* __restrict__ tg_b1,
    const float* __restrict__ tg_W2,  const float* __restrict__ tg_b2,
    const float* __restrict__ sg_W,   const float* __restrict__ sg_b,
    const float* __restrict__ tw_b1,
    const float* __restrict__ tw_W2,  const float* __restrict__ tw_b2,
    const float* __restrict__ tw_W3,  const float* __restrict__ tw_b3,
    float* __restrict__ out)
{
    extern __shared__ char sm[];
    float*    fga   = reinterpret_cast<float*>(sm + OFF_CFP);          // [256][8]
    float*    fgb   = reinterpret_cast<float*>(sm + OFF_CFP + 8192);   // [8][256]
    float*    slab0 = reinterpret_cast<float*>(sm + OFF_A);
    float*    slab1 = reinterpret_cast<float*>(sm + OFF_A + SLAB_BYTES);
    uint32_t* cmw   = reinterpret_cast<uint32_t*>(sm + OFF_CMB);
    uint32_t* aw    = reinterpret_cast<uint32_t*>(sm + OFF_A);
    uint32_t* bw    = reinterpret_cast<uint32_t*>(sm + OFF_B);
    float*    cfp   = reinterpret_cast<float*>(sm + OFF_CFP);
    float*    gwb   = reinterpret_cast<float*>(sm + OFF_GW);
    float*    lgb   = reinterpret_cast<float*>(sm + OFF_B);
    float*    twh2  = reinterpret_cast<float*>(sm + OFF_B);

    const uint32_t wstA[2] = { sm_addr(sm + OFF_WST0), sm_addr(sm + OFF_WST1) };

    const int tid  = threadIdx.x;
    const int wid  = tid >> 5, lane = tid & 31;
    const int t    = blockIdx.y;
    const int g    = t >> 1;                    // TASK_TO_GROUP = {0,0,1,1}
    const int row0 = blockIdx.x * ROWS;
    const float* zg = g ? z_g1 : z_g0;

    // ---- prefetch TG weights into buf0 (overlaps all of gating) ----------
    stage_chunk<64, 32, 32>(wstA[0], g_wimg + ITG + t * 16384, 0, tid);

    // ---- stage fgA [256][8], fgB [8][256] into smem ----------------------
    {
        const float4* A4 = reinterpret_cast<const float4*>(fg_A + (size_t)t * 2048);
        const float4* B4 = reinterpret_cast<const float4*>(fg_B + (size_t)t * 2048);
        reinterpret_cast<float4*>(fga)[tid] = __ldg(&A4[tid]);
        reinterpret_cast<float4*>(fgb)[tid] = __ldg(&B4[tid]);
    }

    // ---- pass 1: double-buffered slab; racc = cm @ fgA; pack UNGATED cm --
    const int grow = tid >> 2;            // 0..127 (row)
    const int jp   = (tid & 3) * 2;       // 0,2,4,6
    float r0 = 0.f, r1 = 0.f;
#pragma unroll
    for (int j = 0; j < 2; j++) {
        const int i = tid + j * THREADS;
        *reinterpret_cast<float4*>(&slab0[(i >> 3) * P_SL + (i & 7) * 4]) =
            *reinterpret_cast<const float4*>(
                z_shared + (size_t)(row0 + (i >> 3)) * META + (i & 7) * 4);
    }
#pragma unroll 1
    for (int ch = 0; ch < 8; ch++) {
        __syncthreads();
        const float* cur = (ch & 1) ? slab1 : slab0;
        float4 zr[2];
        const bool more = (ch < 7);
        if (more) {
            const float* zsrc = (ch + 1 < 4) ? z_shared : zg;
            const int cb = ((ch + 1) & 3) * 32;
#pragma unroll
            for (int j = 0; j < 2; j++) {
                const int i = tid + j * THREADS;
                zr[j] = *reinterpret_cast<const float4*>(
                    zsrc + (size_t)(row0 + (i >> 3)) * META + cb + (i & 7) * 4);
            }
        }
#pragma unroll 8
        for (int k = 0; k < 32; k++) {
            const float a = cur[grow * P_SL + k];
            const float2 f = *reinterpret_cast<const float2*>(
                &fga[(ch * 32 + k) * 8 + jp]);
            r0 = fmaf(a, f.x, r0);
            r1 = fmaf(a, f.y, r1);
        }
#pragma unroll
        for (int i2 = 0; i2 < 4; i2++) {
            const int p = tid + i2 * THREADS;
            const int row = p >> 4, pp = p & 15;
            const float2 v = *reinterpret_cast<const float2*>(
                &cur[row * P_SL + 2 * pp]);
            cmw[row * P_CM + ch * 16 + pp] = packbf(v.x, v.y);
        }
        if (more) {
            float* nxt = (ch & 1) ? slab0 : slab1;
#pragma unroll
            for (int j = 0; j < 2; j++) {
                const int i = tid + j * THREADS;
                *reinterpret_cast<float4*>(&nxt[(i >> 3) * P_SL + (i & 7) * 4]) = zr[j];
            }
        }
    }
    // assemble full r[8] per thread via shuffles (4 threads share a row)
    float rr[8];
    {
        const int lb = lane & ~3;
#pragma unroll
        for (int k2 = 0; k2 < 4; k2++) {
            rr[2 * k2]     = __shfl_sync(0xffffffffu, r0, lb + k2);
            rr[2 * k2 + 1] = __shfl_sync(0xffffffffu, r1, lb + k2);
        }
    }
    __syncthreads();   // cmw pass-1 writes -> pass-2 reads

    // ---- pass 2: gate cmw in place, vectorized (thread = 64 cols of row) --
    {
        uint32_t* cmrow = cmw + grow * P_CM;
        const int cb4 = (tid & 3) * 8;     // uint4 index base (8 uint4 = 64 cols)
#pragma unroll
        for (int u = 0; u < 8; u++) {
            const int i4 = cb4 + u;
            uint4 w4 = *reinterpret_cast<uint4*>(cmrow + i4 * 4);
            const float2 v0 = unpkbf(w4.x), v1 = unpkbf(w4.y);
            const float2 v2 = unpkbf(w4.z), v3 = unpkbf(w4.w);
            float d[8];
#pragma unroll
            for (int q = 0; q < 8; q++) d[q] = 0.f;
#pragma unroll
            for (int j = 0; j < 8; j++) {
                const float rj = rr[j];
                const float4 f0 = *reinterpret_cast<const float4*>(&fgb[j * 256 + i4 * 8]);
                const float4 f1 = *reinterpret_cast<const float4*>(&fgb[j * 256 + i4 * 8 + 4]);
                d[0] = fmaf(rj, f0.x, d[0]); d[1] = fmaf(rj, f0.y, d[1]);
                d[2] = fmaf(rj, f0.z, d[2]); d[3] = fmaf(rj, f0.w, d[3]);
                d[4] = fmaf(rj, f1.x, d[4]); d[5] = fmaf(rj, f1.y, d[5]);
                d[6] = fmaf(rj, f1.z, d[6]); d[7] = fmaf(rj, f1.w, d[7]);
            }
            uint4 o;
            o.x = packbf(v0.x * 2.0f * sigm(d[0]), v0.y * 2.0f * sigm(d[1]));
            o.y = packbf(v1.x * 2.0f * sigm(d[2]), v1.y * 2.0f * sigm(d[3]));
            o.z = packbf(v2.x * 2.0f * sigm(d[4]), v2.y * 2.0f * sigm(d[5]));
            o.w = packbf(v3.x * 2.0f * sigm(d[6]), v3.y * 2.0f * sigm(d[7]));
            *reinterpret_cast<uint4*>(cmrow + i4 * 4) = o;
        }
    }

    // ---- task gate GEMM (buf0), prefetch W1[e0]c0 into buf1 ---------------
    const int e0 = 0;  // first expert index is 0 for all tasks
    cp_wait0();
    __syncthreads();   // TG staged + cmw gated, visible to all
    stage_chunk<128, 16, 32>(wstA[1], g_wimg + IW1 + e0 * 32768, 0, tid);
    {
        float acc[1][4][4];
#pragma unroll
        for (int nt = 0; nt < 4; nt++)
#pragma unroll
            for (int i = 0; i < 4; i++) acc[0][nt][i] = 0.f;
        mma_chunk<64, 256, P_CM>(acc, cmw, wstA[0], 0, tid);
        epilogue<64, true, false, P_CF>(acc, tg_b1 + t * 64, cfp, tid);
    }
    __syncthreads();
    {
        const int row = tid >> 2, j = tid & 3;
        const float* W = tg_W2 + (size_t)t * 64 * 4;
        float acc = __ldg(&tg_b2[t * 4 + j]);
#pragma unroll 4
        for (int c2 = 0; c2 < 64; c2++)
            acc = fmaf(cfp[row * P_CF + c2], __ldg(&W[c2 * 4 + j]), acc);
        lgb[row * 4 + j] = acc;
    }
    __syncthreads();
    if (tid < ROWS) {
        const float l0 = lgb[tid * 4 + 0], l1 = lgb[tid * 4 + 1];
        const float l2 = lgb[tid * 4 + 2], l3 = lgb[tid * 4 + 3];
        const float m  = fmaxf(fmaxf(l0, l1), fmaxf(l2, l3));
        const float e0f = __expf(l0 - m), e1f = __expf(l1 - m);
        const float e2f = __expf(l2 - m), e3f = __expf(l3 - m);
        const float inv = 1.0f / (e0f + e1f + e2f + e3f);
        gwb[tid * 4 + 0] = e0f * inv; gwb[tid * 4 + 1] = e1f * inv;
        gwb[tid * 4 + 2] = e2f * inv; gwb[tid * 4 + 3] = e3f * inv;
    }
    // next sync (W1c0 step) publishes gwb before any reader

    // ---- expert loop: ring-pipelined chunks -------------------------------
    // ring trace: TG(buf0)->W1c0(1)->W1c1(0)->W2(1)->W3(0)->W1'c0(1)->...
    int cur = 1;
    float ag0[8], ag1[8];
#pragma unroll 1
    for (int ep = 0; ep < 4; ep++) {
        const int e = (ep < 2) ? ep : (ep + 2 * g);

        // ---- W1: two 128-K chunks ----
        float acc1[2][4][4];
#pragma unroll
        for (int mt = 0; mt < 2; mt++)
#pragma unroll
            for (int nt = 0; nt < 4; nt++)
#pragma unroll
                for (int i = 0; i < 4; i++) acc1[mt][nt][i] = 0.f;

        cp_wait0(); __syncthreads();
        stage_chunk<128, 16, 32>(wstA[cur ^ 1], g_wimg + IW1 + e * 32768, 1, tid);
        mma_chunk<128, 128, P_CM>(acc1, cmw, wstA[cur], 0, tid);
        cur ^= 1;

        cp_wait0(); __syncthreads();
        stage_chunk<64, 16, 16>(wstA[cur ^ 1], g_wimg + IW2 + e * 8192, 0, tid);
        mma_chunk<128, 128, P_CM>(acc1, cmw, wstA[cur], 1, tid);
        cur ^= 1;
        epilogue<128, true, true, P_A>(acc1, exp_b1 + e * 128, aw, tid);

        // ---- W2 ----
        float acc2[1][4][4];
#pragma unroll
        for (int nt = 0; nt < 4; nt++)
#pragma unroll
            for (int i = 0; i < 4; i++) acc2[0][nt][i] = 0.f;
        cp_wait0(); __syncthreads();
        stage_chunk<64, 8, 8>(wstA[cur ^ 1], g_wimg + IW3 + e * 4096, 0, tid);
        mma_chunk<64, 128, P_A>(acc2, aw, wstA[cur], 0, tid);
        cur ^= 1;
        epilogue<64, true, true, P_B>(acc2, exp_b2 + e * 64, bw, tid);

        // ---- W3 ----
        float acc3[1][4][4];
#pragma unroll
        for (int nt = 0; nt < 4; nt++)
#pragma unroll
            for (int i = 0; i < 4; i++) acc3[0][nt][i] = 0.f;
        cp_wait0(); __syncthreads();
        if (ep < 3) {
            const int en = (ep + 1 < 2) ? (ep + 1) : (ep + 1 + 2 * g);
            stage_chunk<128, 16, 32>(wstA[cur ^ 1], g_wimg + IW1 + en * 32768, 0, tid);
        } else {
            stage_chunk<64, 8, 8>(wstA[cur ^ 1], g_wimg + IT1 + t * 4096, 0, tid);
        }
        mma_chunk<64, 64, P_B>(acc3, bw, wstA[cur], 0, tid);
        cur ^= 1;
        epilogue<64, false, false, P_CF>(acc3, exp_b3 + e * 64, cfp, tid);
        __syncthreads();

        // ---- LN + diag self-gate + softmax aggregation ----
        {
            const float* lS  = ln_s + e * 64;
            const float* lB  = ln_b + e * 64;
            const float* sgw = sg_W + (size_t)t * 256;
            const float  sgb = __ldg(&sg_b[t * 4 + ep]);
            const int c0 = 2 * lane, c1 = 2 * lane + 1;
#pragma unroll
            for (int rr2 = 0; rr2 < 8; rr2++) {
                const int row = wid * 8 + rr2;
                const float2 v = *reinterpret_cast<const float2*>(&cfp[row * P_CF + c0]);
                float sum = v.x + v.y;
                float sq  = fmaf(v.x, v.x, v.y * v.y);
#pragma unroll
                for (int o = 16; o; o >>= 1) {
                    sum += __shfl_xor_sync(0xffffffffu, sum, o);
                    sq  += __shfl_xor_sync(0xffffffffu, sq,  o);
                }
                const float mu  = sum * (1.0f / 64.0f);
                const float var = sq * (1.0f / 64.0f) - mu * mu;
                const float inv = rsqrtf(var + 1e-5f);
                const float n0  = fmaf((v.x - mu) * inv, __ldg(&lS[c0]), __ldg(&lB[c0]));
                const float n1  = fmaf((v.y - mu) * inv, __ldg(&lS[c1]), __ldg(&lB[c1]));
                float swp = fmaf(n0, __ldg(&sgw[c0 * 4 + ep]),
                                 n1 * __ldg(&sgw[c1 * 4 + ep]));
#pragma unroll
                for (int o = 16; o; o >>= 1)
                    swp += __shfl_xor_sync(0xffffffffu, swp, o);
                const float scale = (swp + sgb) * gwb[row * 4 + ep];
                if (ep == 0) { ag0[rr2] = n0 * scale;                ag1[rr2] = n1 * scale; }
                else         { ag0[rr2] = fmaf(n0, scale, ag0[rr2]); ag1[rr2] = fmaf(n1, scale, ag1[rr2]); }
            }
        }
        // next chunk step's barrier orders everything
    }

    // ---- agg -> bf16 bw ----------------------------------------------------
#pragma unroll
    for (int rr2 = 0; rr2 < 8; rr2++) {
        const int row = wid * 8 + rr2;
        bw[row * P_B + lane] = packbf(ag0[rr2], ag1[rr2]);
    }

    // ---- tower layer 1 (staged chunk already in flight) --------------------
    {
        float accT[1][4][4];
#pragma unroll
        for (int nt = 0; nt < 4; nt++)
#pragma unroll
            for (int i = 0; i < 4; i++) accT[0][nt][i] = 0.f;
        cp_wait0(); __syncthreads();
        mma_chunk<64, 64, P_B>(accT, bw, wstA[cur], 0, tid);
        epilogue<64, true, false, P_CF>(accT, tw_b1 + t * 64, cfp, tid);
    }
    __syncthreads();
    gemm_t2(cfp, tw_W2 + (size_t)t * 64 * 32, tw_b2 + t * 32, twh2, tid);
    __syncthreads();
    if (tid < ROWS) {
        const float* th = &twh2[tid * P_B];
        const float* W  = tw_W3 + t * 32;
        float acc = __ldg(&tw_b3[t]);
#pragma unroll 4
        for (int c2 = 0; c2 < 32; c2++)
            acc = fmaf(th[c2], __ldg(&W[c2]), acc);
        out[(size_t)(row0 + tid) * 4 + t] = sigm(acc);
    }
}

extern "C" void kernel_launch(void* const* d_in, const int* in_sizes, int n_in,
                              void* d_out, int out_size)
{
    (void)n_in; (void)out_size;
    const float* zs   = (const float*)d_in[0];
    const float* z0   = (const float*)d_in[1];
    const float* z1   = (const float*)d_in[2];
    const float* eW1  = (const float*)d_in[4];
    const float* eb1  = (const float*)d_in[5];
    const float* eW2  = (const float*)d_in[6];
    const float* eb2  = (const float*)d_in[7];
    const float* eW3  = (const float*)d_in[8];
    const float* eb3  = (const float*)d_in[9];
    const float* lns  = (const float*)d_in[10];
    const float* lnb  = (const float*)d_in[11];
    const float* fgA  = (const float*)d_in[12];
    const float* fgB  = (const float*)d_in[13];
    const float* tgW1 = (const float*)d_in[14];
    const float* tgb1 = (const float*)d_in[15];
    const float* tgW2 = (const float*)d_in[16];
    const float* tgb2 = (const float*)d_in[17];
    const float* sgW  = (const float*)d_in[18];
    const float* sgb  = (const float*)d_in[19];
    const float* twW1 = (const float*)d_in[20];
    const float* twb1 = (const float*)d_in[21];
    const float* twW2 = (const float*)d_in[22];
    const float* twb2 = (const float*)d_in[23];
    const float* twW3 = (const float*)d_in[24];
    const float* twb3 = (const float*)d_in[25];

    const int Bn = in_sizes[0] / META;

    prep_all<<<296, 256>>>(eW1, eW2, eW3, tgW1, twW1);

    cudaFuncSetAttribute(home_kernel, cudaFuncAttributeMaxDynamicSharedMemorySize,
                         SMEM_TOTAL);
    dim3 grid(Bn / ROWS, 4);
    home_kernel<<<grid, THREADS, SMEM_TOTAL>>>(
        zs, z0, z1, eb1, eb2, eb3, lns, lnb, fgA, fgB,
        tgb1, tgW2, tgb2, sgW, sgb, twb1, twW2, twb2, twW3, twb3,
        (float*)d_out);
}